// round 10
// baseline (speedup 1.0000x reference)
#include <cuda_runtime.h>
#include <math.h>
#include <stdint.h>

#define Bsz  64
#define Tlen 2048
#define Hd   128
#define G4   512
#define Cout 7

// ---------------- device scratch ----------------
__device__ float g_v0[G4];
__device__ float g_u0[G4];
__device__ float g_H1[(size_t)Tlen * Bsz * Hd];     // layer-0 h stream [t][b][h]
__device__ float g_G1[(size_t)Tlen * Bsz * G4];     // layer-1 input-gate preacts [t][b][g]
__device__ float g_pool[Bsz * 3 * Hd];

__device__ __forceinline__ float sigf(float x)  { return 1.0f / (1.0f + __expf(-x)); }
__device__ __forceinline__ float tanhfast(float x) {
    return fmaf(-2.0f, 1.0f / (__expf(2.0f * x) + 1.0f), 1.0f);   // = 2*sig(2x)-1
}

// ---- packed f32x2 (Blackwell FFMA2) ----
__device__ __forceinline__ void fma2(unsigned long long& d, unsigned long long a, unsigned long long b) {
    asm("fma.rn.f32x2 %0, %1, %2, %0;" : "+l"(d) : "l"(a), "l"(b));
}
__device__ __forceinline__ float2 upk2(unsigned long long v) {
    float2 r; asm("mov.b64 {%0, %1}, %2;" : "=f"(r.x), "=f"(r.y) : "l"(v)); return r;
}
__device__ __forceinline__ unsigned long long splat2(float f) {
    unsigned long long v; asm("mov.b64 %0, {%1, %1};" : "=l"(v) : "f"(f)); return v;
}

__device__ __forceinline__ uint32_t smem_u32(const void* p) {
    uint32_t a;
    asm("{ .reg .u64 t; cvta.to.shared.u64 t, %1; cvt.u32.u64 %0, t; }" : "=r"(a) : "l"(p));
    return a;
}
__device__ __forceinline__ uint32_t mapa32(uint32_t a, uint32_t rank) {
    uint32_t d;
    asm("mapa.shared::cluster.u32 %0, %1, %2;" : "=r"(d) : "r"(a), "r"(rank));
    return d;
}
__device__ __forceinline__ void st_async_remote(uint32_t raddr, float v, uint32_t rmbar) {
    asm volatile("st.async.shared::cluster.mbarrier::complete_tx::bytes.b32 [%0], %1, [%2];"
                 :: "r"(raddr), "r"(__float_as_uint(v)), "r"(rmbar) : "memory");
}
__device__ __forceinline__ void mbar_init(uint32_t mbar, uint32_t cnt) {
    asm volatile("mbarrier.init.shared.b64 [%0], %1;" :: "r"(mbar), "r"(cnt) : "memory");
}
__device__ __forceinline__ void mbar_expect_tx(uint32_t mbar, uint32_t bytes) {
    asm volatile("mbarrier.arrive.expect_tx.shared.b64 _, [%0], %1;" :: "r"(mbar), "r"(bytes) : "memory");
}
__device__ __forceinline__ void mbar_wait(uint32_t mbar, uint32_t parity) {
    uint32_t done;
    asm volatile(
        "{\n\t.reg .pred p;\n\t"
        "mbarrier.try_wait.parity.acquire.cluster.shared::cta.b64 p, [%1], %2;\n\t"
        "selp.b32 %0, 1, 0, p;\n\t}"
        : "=r"(done) : "r"(mbar), "r"(parity) : "memory");
    if (!done) {
        asm volatile(
            "{\n\t.reg .pred P1;\n\t"
            "WL_%=:\n\t"
            "mbarrier.try_wait.parity.acquire.cluster.shared::cta.b64 P1, [%0], %1, 0x989680;\n\t"
            "@P1 bra.uni WD_%=;\n\t"
            "bra.uni WL_%=;\n\t"
            "WD_%=:\n\t}"
            :: "r"(mbar), "r"(parity) : "memory");
    }
}

// ---------------- prep ----------------
__global__ void prep_kernel(const float* __restrict__ Wih0, const float* __restrict__ ffw,
                            const float* __restrict__ ffb,  const float* __restrict__ b0) {
    int g = blockIdx.x * 64 + threadIdx.x;   // 8 * 64
    float v = 0.f, u = 0.f;
    #pragma unroll 8
    for (int k = 0; k < Hd; k++) {
        float w = Wih0[g * Hd + k];
        v = fmaf(w, ffw[k], v);
        u = fmaf(w, ffb[k], u);
    }
    g_v0[g] = v;
    g_u0[g] = u + b0[g];
}

// ---------------- lane-interleaved h-split cluster LSTM ----------------
// 64 clusters of 2 CTAs. hloc = tid>>2, type = tid&3 -> the 4 gates of one h
// sit in 4 ADJACENT LANES: act exchange is 4 shuffles (no smem, no barrier).
// c,h computed redundantly in all 4 lanes (bit-identical). ONE syncthreads/step.
// Matvec: local k-half first (hides DSMEM flight of peer h), mbar wait, remote half.
template <int LAYER>
__global__ __launch_bounds__(256, 1) __cluster_dims__(2, 1, 1)
void lstm_kernel(const float* __restrict__ Whh,
                 const float* __restrict__ xin,
                 const int*   __restrict__ lengths) {
    __shared__ __align__(16) float h_s[2][Hd];     // parity double-buffered h
    __shared__ float xrow[Tlen];
    __shared__ __align__(8) unsigned long long mbar[2];

    const int tid   = threadIdx.x;
    const int rank  = blockIdx.x & 1;
    const int b     = blockIdx.x >> 1;
    const int hloc  = tid >> 2;                    // 0..63
    const int type  = tid & 3;                     // 0=i 1=f 2=g 3=o
    const int h_idx = 64 * rank + hloc;
    const int g     = type * 128 + h_idx;          // PyTorch gate order
    const int kloc  = 64 * rank;
    const int krem  = 64 * (1 - rank);
    const bool isG  = (type == 2);

    // ---- weights: local k-half in w2[0..16), remote in w2[16..32) ----
    ulonglong2 w2[32];
    #pragma unroll
    for (int q = 0; q < 16; q++)
        w2[q] = *(const ulonglong2*)(Whh + (size_t)g * Hd + kloc + 4 * q);
    #pragma unroll
    for (int q = 0; q < 16; q++)
        w2[16 + q] = *(const ulonglong2*)(Whh + (size_t)g * Hd + krem + 4 * q);

    uint32_t mb0 = smem_u32(&mbar[0]);
    uint32_t mb1 = smem_u32(&mbar[1]);
    if (tid == 0) {
        mbar_init(mb0, 1); mbar_init(mb1, 1);
        mbar_expect_tx(mb0, 256); mbar_expect_tx(mb1, 256);   // 64 floats per step
    }
    const uint32_t peer = rank ^ 1;
    const uint32_t r_h0  = mapa32(smem_u32(&h_s[0][h_idx]), peer);
    const uint32_t r_h1  = mapa32(smem_u32(&h_s[1][h_idx]), peer);
    const uint32_t r_mb0 = mapa32(mb0, peer);
    const uint32_t r_mb1 = mapa32(mb1, peer);

    float vg = 0.f, ug = 0.f;
    if (LAYER == 0) {
        vg = g_v0[g]; ug = g_u0[g];
        for (int i = tid; i < Tlen; i += 256) xrow[i] = xin[(size_t)b * Tlen + i];
    }
    if (tid < Hd) h_s[0][tid] = 0.f;
    __syncthreads();
    asm volatile("barrier.cluster.arrive.aligned;" ::: "memory");
    asm volatile("barrier.cluster.wait.aligned;" ::: "memory");

    float cst = 0.f, sum = 0.f, mx = -INFINITY, last = 0.f;
    const int len = lengths[b];
    uint32_t ph0 = 0, ph1 = 0;

    float zn = 0.f;
    if (LAYER == 1) zn = g_G1[(size_t)b * G4 + g];   // prefetch t=0

    const int lane = tid & 31;
    const int lbase = lane & ~3;

    for (int t = 0; t < Tlen; t++) {
        const int p  = t & 1;
        const int pn = p ^ 1;

        float a_in;
        if (LAYER == 0) {
            a_in = fmaf(xrow[t], vg, ug);
        } else {
            a_in = zn;
            if (t + 1 < Tlen) zn = g_G1[((size_t)(t + 1) * Bsz + b) * G4 + g];
        }

        const ulonglong2* hp = (const ulonglong2*)h_s[p];
        const ulonglong2* hL = hp + (kloc >> 2);
        const ulonglong2* hR = hp + (krem >> 2);

        // ---- local k-half (peer h still in flight) ----
        unsigned long long acc0 = 0ULL, acc1 = 0ULL;
        #pragma unroll
        for (int q = 0; q < 16; q++) {
            ulonglong2 hv = hL[q];
            fma2(acc0, hv.x, w2[q].x);
            fma2(acc1, hv.y, w2[q].y);
        }
        // ---- wait for peer's 64 h values, then remote k-half ----
        if (t > 0) {
            if (p == 0) { mbar_wait(mb0, ph0); ph0 ^= 1; }
            else        { mbar_wait(mb1, ph1); ph1 ^= 1; }
            if (tid == 0) mbar_expect_tx(p ? mb1 : mb0, 256);   // re-arm for t+2
        }
        #pragma unroll
        for (int q = 0; q < 16; q++) {
            ulonglong2 hv = hR[q];
            fma2(acc0, hv.x, w2[16 + q].x);
            fma2(acc1, hv.y, w2[16 + q].y);
        }
        float2 u0 = upk2(acc0), u1 = upk2(acc1);
        float A = a_in + ((u0.x + u0.y) + (u1.x + u1.y));

        // unified activation: sig for i,f,o; tanh(A)=2*sig(2A)-1 for g -> ONE MUFU chain
        float Ax = isG ? (A + A) : A;
        float s  = sigf(Ax);
        float av = isG ? fmaf(2.f, s, -1.f) : s;

        // act exchange via shuffles (lanes 4j..4j+3 hold i,f,g,o of h=j)
        float iv = __shfl_sync(0xffffffffu, av, lbase + 0);
        float fv = __shfl_sync(0xffffffffu, av, lbase + 1);
        float gv = __shfl_sync(0xffffffffu, av, lbase + 2);
        float ov = __shfl_sync(0xffffffffu, av, lbase + 3);

        // redundant (bit-identical) cell/hidden update in all 4 lanes
        cst = fmaf(fv, cst, iv * gv);
        float h = ov * tanhfast(cst);

        if (type == 0) {
            st_async_remote(pn ? r_h1 : r_h0, h, pn ? r_mb1 : r_mb0);  // flight first
            h_s[pn][h_idx] = h;
            if (LAYER == 0) {
                g_H1[((size_t)t * Bsz + b) * Hd + h_idx] = h;
            } else {
                if (t < len) { sum += h; mx = fmaxf(mx, h); }
                if (t == len - 1) last = h;
            }
        }
        __syncthreads();   // h_s[pn] locally visible for next step's local half
    }

    if (LAYER == 1 && type == 0) {
        g_pool[b * 384 + h_idx]            = sum / (float)len;
        g_pool[b * 384 + Hd + h_idx]       = mx;
        g_pool[b * 384 + 2 * Hd + h_idx]   = last;
    }
    asm volatile("barrier.cluster.arrive.aligned;" ::: "memory");
    asm volatile("barrier.cluster.wait.aligned;" ::: "memory");
}

// ---------------- GEMM on FFMA2: G1 = H1 @ Wih1^T + b1 (M=131072, N=512, K=128) ----
__global__ __launch_bounds__(256)
void gemm_g1_kernel(const float* __restrict__ Wih1, const float* __restrict__ b1) {
    __shared__ float As[16][128];
    __shared__ float Bs[16][128];
    const int m0 = blockIdx.x * 128;
    const int n0 = blockIdx.y * 128;
    const int tid = threadIdx.x;
    const int tr = (tid >> 4) * 8;
    const int tc = (tid & 15) * 8;

    unsigned long long acc2[8][4];
    #pragma unroll
    for (int i = 0; i < 8; i++)
        #pragma unroll
        for (int j = 0; j < 4; j++) acc2[i][j] = 0ULL;

    for (int k0 = 0; k0 < 128; k0 += 16) {
        for (int l = tid; l < 512; l += 256) {
            int row = l >> 2, c4 = (l & 3) * 4;
            float4 v = *(const float4*)(g_H1 + (size_t)(m0 + row) * 128 + k0 + c4);
            As[c4 + 0][row] = v.x; As[c4 + 1][row] = v.y;
            As[c4 + 2][row] = v.z; As[c4 + 3][row] = v.w;
        }
        for (int l = tid; l < 512; l += 256) {
            int row = l >> 2, c4 = (l & 3) * 4;
            float4 v = *(const float4*)(Wih1 + (size_t)(n0 + row) * 128 + k0 + c4);
            Bs[c4 + 0][row] = v.x; Bs[c4 + 1][row] = v.y;
            Bs[c4 + 2][row] = v.z; Bs[c4 + 3][row] = v.w;
        }
        __syncthreads();
        #pragma unroll
        for (int kk = 0; kk < 16; kk++) {
            float4 a0 = *(const float4*)&As[kk][tr];
            float4 a1 = *(const float4*)&As[kk][tr + 4];
            ulonglong2 bp0 = *(const ulonglong2*)&Bs[kk][tc];
            ulonglong2 bp1 = *(const ulonglong2*)&Bs[kk][tc + 4];
            float ra[8] = {a0.x, a0.y, a0.z, a0.w, a1.x, a1.y, a1.z, a1.w};
            #pragma unroll
            for (int i = 0; i < 8; i++) {
                unsigned long long as = splat2(ra[i]);
                fma2(acc2[i][0], as, bp0.x);
                fma2(acc2[i][1], as, bp0.y);
                fma2(acc2[i][2], as, bp1.x);
                fma2(acc2[i][3], as, bp1.y);
            }
        }
        __syncthreads();
    }
    #pragma unroll
    for (int i = 0; i < 8; i++) {
        #pragma unroll
        for (int j = 0; j < 2; j++) {
            float2 p0 = upk2(acc2[i][2 * j]);
            float2 p1 = upk2(acc2[i][2 * j + 1]);
            float4 v;
            v.x = p0.x + b1[n0 + tc + 4 * j + 0];
            v.y = p0.y + b1[n0 + tc + 4 * j + 1];
            v.z = p1.x + b1[n0 + tc + 4 * j + 2];
            v.w = p1.y + b1[n0 + tc + 4 * j + 3];
            *(float4*)(g_G1 + (size_t)(m0 + tr + i) * G4 + n0 + tc + 4 * j) = v;
        }
    }
}

// ---------------- final linear: 64 CTAs, warp w -> class w ----------------
__global__ __launch_bounds__(256)
void final_kernel(const float* __restrict__ lw, const float* __restrict__ lb,
                  float* __restrict__ out) {
    const int b = blockIdx.x;
    const int wid = threadIdx.x >> 5;
    const int lane = threadIdx.x & 31;
    if (wid >= Cout) return;
    float s = 0.f;
    const float* p = g_pool + b * 384;
    const float* wv = lw + wid * 384;
    #pragma unroll
    for (int j = lane; j < 384; j += 32) s = fmaf(p[j], wv[j], s);
    #pragma unroll
    for (int o = 16; o > 0; o >>= 1) s += __shfl_xor_sync(0xffffffff, s, o);
    if (lane == 0) out[b * Cout + wid] = s + lb[wid];
}

// ---------------- launch ----------------
extern "C" void kernel_launch(void* const* d_in, const int* in_sizes, int n_in,
                              void* d_out, int out_size) {
    const float* x    = (const float*)d_in[0];
    const int*   lens = (const int*)  d_in[1];
    const float* ffw  = (const float*)d_in[2];
    const float* ffb  = (const float*)d_in[3];
    const float* Wih0 = (const float*)d_in[4];
    const float* Whh0 = (const float*)d_in[5];
    const float* b0   = (const float*)d_in[6];
    const float* Wih1 = (const float*)d_in[7];
    const float* Whh1 = (const float*)d_in[8];
    const float* b1   = (const float*)d_in[9];
    const float* lw   = (const float*)d_in[10];
    const float* lb   = (const float*)d_in[11];
    float* out = (float*)d_out;

    prep_kernel<<<8, 64>>>(Wih0, ffw, ffb, b0);
    lstm_kernel<0><<<2 * Bsz, 256>>>(Whh0, x, lens);
    dim3 ggrid((Tlen * Bsz) / 128, G4 / 128);
    gemm_g1_kernel<<<ggrid, 256>>>(Wih1, b1);
    lstm_kernel<1><<<2 * Bsz, 256>>>(Whh1, x, lens);
    final_kernel<<<Bsz, 256>>>(lw, lb, out);
}

// round 11
// speedup vs baseline: 1.1108x; 1.1108x over previous
#include <cuda_runtime.h>
#include <math.h>
#include <stdint.h>

#define Bsz  64
#define Tlen 2048
#define Hd   128
#define G4   512
#define Cout 7

// ---------------- device scratch ----------------
__device__ float g_v0[G4];
__device__ float g_u0[G4];
__device__ float g_H1[(size_t)Tlen * Bsz * Hd];     // layer-0 h stream [t][b][h]
__device__ float g_G1[(size_t)Tlen * Bsz * G4];     // layer-1 input-gate preacts [t][b][g]
__device__ float g_pool[Bsz * 3 * Hd];

__device__ __forceinline__ float sigf(float x)  { return 1.0f / (1.0f + __expf(-x)); }
__device__ __forceinline__ float tanhfast(float x) {
    return fmaf(-2.0f, 1.0f / (__expf(2.0f * x) + 1.0f), 1.0f);
}

// ---- packed f32x2 (Blackwell FFMA2) ----
__device__ __forceinline__ void fma2(unsigned long long& d, unsigned long long a, unsigned long long b) {
    asm("fma.rn.f32x2 %0, %1, %2, %0;" : "+l"(d) : "l"(a), "l"(b));
}
__device__ __forceinline__ float2 upk2(unsigned long long v) {
    float2 r; asm("mov.b64 {%0, %1}, %2;" : "=f"(r.x), "=f"(r.y) : "l"(v)); return r;
}

// ---- tf32 helpers ----
__device__ __forceinline__ uint32_t f2tf(float f) {
    uint32_t r; asm("cvt.rna.tf32.f32 %0, %1;" : "=r"(r) : "f"(f)); return r;
}
__device__ __forceinline__ void mma_tf32(float* c, const uint32_t* a, const uint32_t* b) {
    asm("mma.sync.aligned.m16n8k8.row.col.f32.tf32.tf32.f32 "
        "{%0,%1,%2,%3}, {%4,%5,%6,%7}, {%8,%9}, {%0,%1,%2,%3};"
        : "+f"(c[0]), "+f"(c[1]), "+f"(c[2]), "+f"(c[3])
        : "r"(a[0]), "r"(a[1]), "r"(a[2]), "r"(a[3]), "r"(b[0]), "r"(b[1]));
}

__device__ __forceinline__ uint32_t smem_u32(const void* p) {
    uint32_t a;
    asm("{ .reg .u64 t; cvta.to.shared.u64 t, %1; cvt.u32.u64 %0, t; }" : "=r"(a) : "l"(p));
    return a;
}
__device__ __forceinline__ uint32_t mapa32(uint32_t a, uint32_t rank) {
    uint32_t d;
    asm("mapa.shared::cluster.u32 %0, %1, %2;" : "=r"(d) : "r"(a), "r"(rank));
    return d;
}
__device__ __forceinline__ void st_async_remote(uint32_t raddr, float v, uint32_t rmbar) {
    asm volatile("st.async.shared::cluster.mbarrier::complete_tx::bytes.b32 [%0], %1, [%2];"
                 :: "r"(raddr), "r"(__float_as_uint(v)), "r"(rmbar) : "memory");
}
__device__ __forceinline__ void mbar_init(uint32_t mbar, uint32_t cnt) {
    asm volatile("mbarrier.init.shared.b64 [%0], %1;" :: "r"(mbar), "r"(cnt) : "memory");
}
__device__ __forceinline__ void mbar_expect_tx(uint32_t mbar, uint32_t bytes) {
    asm volatile("mbarrier.arrive.expect_tx.shared.b64 _, [%0], %1;" :: "r"(mbar), "r"(bytes) : "memory");
}
__device__ __forceinline__ void mbar_wait(uint32_t mbar, uint32_t parity) {
    uint32_t done;
    asm volatile(
        "{\n\t.reg .pred p;\n\t"
        "mbarrier.try_wait.parity.acquire.cluster.shared::cta.b64 p, [%1], %2;\n\t"
        "selp.b32 %0, 1, 0, p;\n\t}"
        : "=r"(done) : "r"(mbar), "r"(parity) : "memory");
    if (!done) {
        asm volatile(
            "{\n\t.reg .pred P1;\n\t"
            "WL_%=:\n\t"
            "mbarrier.try_wait.parity.acquire.cluster.shared::cta.b64 P1, [%0], %1, 0x989680;\n\t"
            "@P1 bra.uni WD_%=;\n\t"
            "bra.uni WL_%=;\n\t"
            "WD_%=:\n\t}"
            :: "r"(mbar), "r"(parity) : "memory");
    }
}

// ---------------- prep ----------------
__global__ void prep_kernel(const float* __restrict__ Wih0, const float* __restrict__ ffw,
                            const float* __restrict__ ffb,  const float* __restrict__ b0) {
    int g = blockIdx.x * 64 + threadIdx.x;
    float v = 0.f, u = 0.f;
    #pragma unroll 8
    for (int k = 0; k < Hd; k++) {
        float w = Wih0[g * Hd + k];
        v = fmaf(w, ffw[k], v);
        u = fmaf(w, ffb[k], u);
    }
    g_v0[g] = v;
    g_u0[g] = u + b0[g];
}

// ---------------- h-split cluster LSTM (R9, best measured) ----------------
template <int LAYER>
__global__ __launch_bounds__(256, 1) __cluster_dims__(2, 1, 1)
void lstm_kernel(const float* __restrict__ Whh,
                 const float* __restrict__ xin,
                 const int*   __restrict__ lengths) {
    __shared__ __align__(16) float h_s[2][Hd];
    __shared__ float act_s[256];
    __shared__ float xrow[Tlen];
    __shared__ __align__(8) unsigned long long mbar[2];

    const int tid  = threadIdx.x;
    const int rank = blockIdx.x & 1;
    const int b    = blockIdx.x >> 1;
    const int type = tid >> 6;
    const int hloc = tid & 63;
    const int h_idx = 64 * rank + hloc;
    const int g    = type * 128 + h_idx;
    const int kloc = 64 * rank;
    const int krem = 64 * (1 - rank);

    ulonglong2 w2[32];
    #pragma unroll
    for (int q = 0; q < 16; q++)
        w2[q] = *(const ulonglong2*)(Whh + (size_t)g * Hd + kloc + 4 * q);
    #pragma unroll
    for (int q = 0; q < 16; q++)
        w2[16 + q] = *(const ulonglong2*)(Whh + (size_t)g * Hd + krem + 4 * q);

    uint32_t mb0 = smem_u32(&mbar[0]);
    uint32_t mb1 = smem_u32(&mbar[1]);
    if (tid == 0) {
        mbar_init(mb0, 1); mbar_init(mb1, 1);
        mbar_expect_tx(mb0, 256); mbar_expect_tx(mb1, 256);
    }
    const uint32_t peer = rank ^ 1;
    const uint32_t r_h0  = mapa32(smem_u32(&h_s[0][h_idx]), peer);
    const uint32_t r_h1  = mapa32(smem_u32(&h_s[1][h_idx]), peer);
    const uint32_t r_mb0 = mapa32(mb0, peer);
    const uint32_t r_mb1 = mapa32(mb1, peer);

    float vg = 0.f, ug = 0.f;
    if (LAYER == 0) {
        vg = g_v0[g]; ug = g_u0[g];
        for (int i = tid; i < Tlen; i += 256) xrow[i] = xin[(size_t)b * Tlen + i];
    }
    if (tid < Hd) h_s[0][tid] = 0.f;
    __syncthreads();
    asm volatile("barrier.cluster.arrive.aligned;" ::: "memory");
    asm volatile("barrier.cluster.wait.aligned;" ::: "memory");

    float cst = 0.f, sum = 0.f, mx = -INFINITY, last = 0.f;
    const int len = lengths[b];
    uint32_t ph0 = 0, ph1 = 0;

    float zn = 0.f;
    if (LAYER == 1) zn = g_G1[(size_t)b * G4 + g];

    for (int t = 0; t < Tlen; t++) {
        const int p  = t & 1;
        const int pn = p ^ 1;

        float a_in;
        if (LAYER == 0) {
            a_in = fmaf(xrow[t], vg, ug);
        } else {
            a_in = zn;
            if (t + 1 < Tlen) zn = g_G1[((size_t)(t + 1) * Bsz + b) * G4 + g];
        }

        const ulonglong2* hp = (const ulonglong2*)h_s[p];
        const ulonglong2* hL = hp + (kloc >> 2);
        const ulonglong2* hR = hp + (krem >> 2);

        unsigned long long acc0 = 0ULL, acc1 = 0ULL;
        #pragma unroll
        for (int q = 0; q < 16; q++) {
            ulonglong2 hv = hL[q];
            fma2(acc0, hv.x, w2[q].x);
            fma2(acc1, hv.y, w2[q].y);
        }
        if (t > 0) {
            if (p == 0) { mbar_wait(mb0, ph0); ph0 ^= 1; }
            else        { mbar_wait(mb1, ph1); ph1 ^= 1; }
            if (tid == 0) mbar_expect_tx(p ? mb1 : mb0, 256);
        }
        #pragma unroll
        for (int q = 0; q < 16; q++) {
            ulonglong2 hv = hR[q];
            fma2(acc0, hv.x, w2[16 + q].x);
            fma2(acc1, hv.y, w2[16 + q].y);
        }
        float2 u0 = upk2(acc0), u1 = upk2(acc1);
        float A = a_in + ((u0.x + u0.y) + (u1.x + u1.y));

        float av = (type == 2) ? tanhfast(A) : sigf(A);
        act_s[tid] = av;
        __syncthreads();

        if (tid < 64) {
            float iv = act_s[tid],       fv = act_s[64 + tid];
            float gv = act_s[128 + tid], ov = act_s[192 + tid];
            cst = fmaf(fv, cst, iv * gv);
            float h = ov * tanhfast(cst);
            st_async_remote(pn ? r_h1 : r_h0, h, pn ? r_mb1 : r_mb0);
            h_s[pn][h_idx] = h;
            if (LAYER == 0) {
                g_H1[((size_t)t * Bsz + b) * Hd + h_idx] = h;
            } else {
                if (t < len) { sum += h; mx = fmaxf(mx, h); }
                if (t == len - 1) last = h;
            }
        }
        __syncthreads();
    }

    if (LAYER == 1 && tid < 64) {
        g_pool[b * 384 + h_idx]            = sum / (float)len;
        g_pool[b * 384 + Hd + h_idx]       = mx;
        g_pool[b * 384 + 2 * Hd + h_idx]   = last;
    }
    asm volatile("barrier.cluster.arrive.aligned;" ::: "memory");
    asm volatile("barrier.cluster.wait.aligned;" ::: "memory");
}

// ---------------- TF32 tensor-core GEMM: G1 = H1 @ Wih1^T + b1 ----------------
// M=131072, N=512, K=128. CTA tile 128x128, 8 warps (4 m x 2 n), warp tile 32x64.
// K processed in 4 chunks of 32; tf32 conversion on smem fill.
#define AS_STRIDE 36
#define BS_STRIDE 132
__global__ __launch_bounds__(256)
void gemm_g1_kernel(const float* __restrict__ Wih1, const float* __restrict__ b1) {
    __shared__ uint32_t As[128 * AS_STRIDE];   // [m][k] tf32, 18.4 KB
    __shared__ uint32_t Bs[32 * BS_STRIDE];    // [k][n] tf32, 16.9 KB

    const int m0 = blockIdx.x * 128;
    const int n0 = blockIdx.y * 128;
    const int tid = threadIdx.x;
    const int wid = tid >> 5;
    const int lane = tid & 31;
    const int m_off = (wid & 3) * 32;
    const int n_off = (wid >> 2) * 64;
    const int lr = lane >> 2;      // 0..7
    const int lc = lane & 3;       // 0..3

    float acc[2][8][4];
    #pragma unroll
    for (int mt = 0; mt < 2; mt++)
        #pragma unroll
        for (int nt = 0; nt < 8; nt++)
            #pragma unroll
            for (int i = 0; i < 4; i++) acc[mt][nt][i] = 0.f;

    for (int k0 = 0; k0 < 128; k0 += 32) {
        // fill As: H1[m0+r][k0+c], thread r = tid>>1, cols (tid&1)*16 + 16
        {
            int r = tid >> 1, cs = (tid & 1) * 16;
            const float* src = g_H1 + (size_t)(m0 + r) * 128 + k0 + cs;
            #pragma unroll
            for (int i = 0; i < 4; i++) {
                float4 v = *(const float4*)(src + 4 * i);
                uint4 tv = make_uint4(f2tf(v.x), f2tf(v.y), f2tf(v.z), f2tf(v.w));
                *(uint4*)&As[r * AS_STRIDE + cs + 4 * i] = tv;
            }
        }
        // fill Bs transposed: Bs[k][n] = Wih1[n0+n][k0+k]
        {
            int n = tid >> 1, ks = (tid & 1) * 16;
            const float* src = Wih1 + (size_t)(n0 + n) * 128 + k0 + ks;
            #pragma unroll
            for (int i = 0; i < 4; i++) {
                float4 v = *(const float4*)(src + 4 * i);
                Bs[(ks + 4 * i + 0) * BS_STRIDE + n] = f2tf(v.x);
                Bs[(ks + 4 * i + 1) * BS_STRIDE + n] = f2tf(v.y);
                Bs[(ks + 4 * i + 2) * BS_STRIDE + n] = f2tf(v.z);
                Bs[(ks + 4 * i + 3) * BS_STRIDE + n] = f2tf(v.w);
            }
        }
        __syncthreads();

        #pragma unroll
        for (int ks = 0; ks < 4; ks++) {
            const int kk = ks * 8;
            uint32_t af[2][4];
            #pragma unroll
            for (int mt = 0; mt < 2; mt++) {
                int row = m_off + mt * 16 + lr;
                af[mt][0] = As[row * AS_STRIDE + kk + lc];
                af[mt][1] = As[(row + 8) * AS_STRIDE + kk + lc];
                af[mt][2] = As[row * AS_STRIDE + kk + lc + 4];
                af[mt][3] = As[(row + 8) * AS_STRIDE + kk + lc + 4];
            }
            #pragma unroll
            for (int nt = 0; nt < 8; nt++) {
                int col = n_off + nt * 8 + lr;
                uint32_t bf[2];
                bf[0] = Bs[(kk + lc) * BS_STRIDE + col];
                bf[1] = Bs[(kk + lc + 4) * BS_STRIDE + col];
                mma_tf32(acc[0][nt], af[0], bf);
                mma_tf32(acc[1][nt], af[1], bf);
            }
        }
        __syncthreads();
    }

    // epilogue: c0,c1 -> (row, 2*lc), (row, 2*lc+1); c2,c3 -> row+8
    #pragma unroll
    for (int mt = 0; mt < 2; mt++) {
        #pragma unroll
        for (int nt = 0; nt < 8; nt++) {
            int row = m0 + m_off + mt * 16 + lr;
            int col = n0 + n_off + nt * 8 + 2 * lc;
            float bz0 = b1[col], bz1 = b1[col + 1];
            float2 v0 = make_float2(acc[mt][nt][0] + bz0, acc[mt][nt][1] + bz1);
            float2 v1 = make_float2(acc[mt][nt][2] + bz0, acc[mt][nt][3] + bz1);
            *(float2*)(g_G1 + (size_t)row * G4 + col)       = v0;
            *(float2*)(g_G1 + (size_t)(row + 8) * G4 + col) = v1;
        }
    }
}

// ---------------- final linear ----------------
__global__ __launch_bounds__(256)
void final_kernel(const float* __restrict__ lw, const float* __restrict__ lb,
                  float* __restrict__ out) {
    const int b = blockIdx.x;
    const int wid = threadIdx.x >> 5;
    const int lane = threadIdx.x & 31;
    if (wid >= Cout) return;
    float s = 0.f;
    const float* p = g_pool + b * 384;
    const float* wv = lw + wid * 384;
    #pragma unroll
    for (int j = lane; j < 384; j += 32) s = fmaf(p[j], wv[j], s);
    #pragma unroll
    for (int o = 16; o > 0; o >>= 1) s += __shfl_xor_sync(0xffffffff, s, o);
    if (lane == 0) out[b * Cout + wid] = s + lb[wid];
}

// ---------------- launch ----------------
extern "C" void kernel_launch(void* const* d_in, const int* in_sizes, int n_in,
                              void* d_out, int out_size) {
    const float* x    = (const float*)d_in[0];
    const int*   lens = (const int*)  d_in[1];
    const float* ffw  = (const float*)d_in[2];
    const float* ffb  = (const float*)d_in[3];
    const float* Wih0 = (const float*)d_in[4];
    const float* Whh0 = (const float*)d_in[5];
    const float* b0   = (const float*)d_in[6];
    const float* Wih1 = (const float*)d_in[7];
    const float* Whh1 = (const float*)d_in[8];
    const float* b1   = (const float*)d_in[9];
    const float* lw   = (const float*)d_in[10];
    const float* lb   = (const float*)d_in[11];
    float* out = (float*)d_out;

    prep_kernel<<<8, 64>>>(Wih0, ffw, ffb, b0);
    lstm_kernel<0><<<2 * Bsz, 256>>>(Whh0, x, lens);
    dim3 ggrid((Tlen * Bsz) / 128, G4 / 128);
    gemm_g1_kernel<<<ggrid, 256>>>(Wih1, b1);
    lstm_kernel<1><<<2 * Bsz, 256>>>(Whh1, x, lens);
    final_kernel<<<Bsz, 256>>>(lw, lb, out);
}